// round 17
// baseline (speedup 1.0000x reference)
#include <cuda_runtime.h>
#include <cuda.h>
#include <cuda_fp16.h>
#include <math.h>
#include <stdint.h>

#define BB 2
#define LL 4096
#define DD 512
#define HH 8
#define DKK 64
#define MROWS (BB*LL)          // 8192
#define QKVN (3*DD)            // 1536
#define CC (0.125f * 1.4426950408889634f)

// Scratch (allocation-free rule: __device__ globals)
__device__ __half g_x[(size_t)MROWS * DD];
__device__ __half g_wqkv[(size_t)QKVN * DD];
__device__ __half g_wo[(size_t)DD * DD];
__device__ __half g_qkv[(size_t)MROWS * QKVN];
__device__ __half g_ctx[(size_t)MROWS * DD];

// ---------------------------------------------------------------------------
// Helpers
// ---------------------------------------------------------------------------
__device__ __forceinline__ float ex2(float x) {
    float y;
    asm("ex2.approx.ftz.f32 %0, %1;" : "=f"(y) : "f"(x));
    return y;
}

__device__ __forceinline__ uint32_t pack_h2(float lo, float hi) {
    uint32_t r;
    asm("cvt.rn.f16x2.f32 %0, %1, %2;" : "=r"(r) : "f"(hi), "f"(lo));
    return r;
}

__device__ __forceinline__ void mma_f16(float c[4],
    uint32_t a0, uint32_t a1, uint32_t a2, uint32_t a3,
    uint32_t b0, uint32_t b1)
{
    asm volatile(
        "mma.sync.aligned.m16n8k16.row.col.f32.f16.f16.f32 "
        "{%0,%1,%2,%3}, {%4,%5,%6,%7}, {%8,%9}, {%0,%1,%2,%3};"
        : "+f"(c[0]), "+f"(c[1]), "+f"(c[2]), "+f"(c[3])
        : "r"(a0), "r"(a1), "r"(a2), "r"(a3), "r"(b0), "r"(b1));
}

__device__ __forceinline__ void ldsm4(uint32_t& r0, uint32_t& r1,
                                      uint32_t& r2, uint32_t& r3, uint32_t addr)
{
    asm volatile("ldmatrix.sync.aligned.m8n8.x4.shared.b16 {%0,%1,%2,%3}, [%4];"
                 : "=r"(r0), "=r"(r1), "=r"(r2), "=r"(r3) : "r"(addr));
}

__device__ __forceinline__ void ldsm4t(uint32_t& r0, uint32_t& r1,
                                       uint32_t& r2, uint32_t& r3, uint32_t addr)
{
    asm volatile("ldmatrix.sync.aligned.m8n8.x4.trans.shared.b16 {%0,%1,%2,%3}, [%4];"
                 : "=r"(r0), "=r"(r1), "=r"(r2), "=r"(r3) : "r"(addr));
}

__device__ __forceinline__ uint32_t smem_u32(const void* p) {
    uint32_t a;
    asm("{ .reg .u64 t; cvta.to.shared.u64 t, %1; cvt.u32.u64 %0, t; }"
        : "=r"(a) : "l"(p));
    return a;
}

__device__ __forceinline__ void cp16s(uint32_t smem_addr, const void* gptr) {
    asm volatile("cp.async.cg.shared.global [%0], [%1], 16;"
                 :: "r"(smem_addr), "l"(gptr));
}

// SW128 swizzle (matches CU_TENSOR_MAP_SWIZZLE_128B for 128B rows)
#define SWZ(x) ((x) ^ (((x) >> 3) & 0x70))

// mbarrier ops
__device__ __forceinline__ void mbar_init(uint32_t addr, uint32_t cnt) {
    asm volatile("mbarrier.init.shared.b64 [%0], %1;" :: "r"(addr), "r"(cnt) : "memory");
}
__device__ __forceinline__ void mbar_expect(uint32_t addr, uint32_t bytes) {
    asm volatile("mbarrier.arrive.expect_tx.shared.b64 _, [%0], %1;"
                 :: "r"(addr), "r"(bytes) : "memory");
}
__device__ __forceinline__ void mbar_wait(uint32_t addr, uint32_t parity) {
    uint32_t done;
    asm volatile(
        "{\n\t.reg .pred p;\n\t"
        "mbarrier.try_wait.parity.acquire.cta.shared::cta.b64 p, [%1], %2;\n\t"
        "selp.b32 %0, 1, 0, p;\n\t}"
        : "=r"(done) : "r"(addr), "r"(parity) : "memory");
    if (!done) {
        asm volatile(
            "{\n\t.reg .pred P1;\n\t"
            "WL_%=:\n\t"
            "mbarrier.try_wait.parity.acquire.cta.shared::cta.b64 P1, [%0], %1, 0x989680;\n\t"
            "@P1 bra.uni WD_%=;\n\t"
            "bra.uni WL_%=;\n\t"
            "WD_%=:\n\t}"
            :: "r"(addr), "r"(parity) : "memory");
    }
}

// TMA 2D load (global -> shared::cta, mbarrier complete_tx)
__device__ __forceinline__ void tma2d(uint32_t smem, const CUtensorMap* tm,
                                      int x, int y, uint32_t mbar)
{
    asm volatile(
        "cp.async.bulk.tensor.2d.shared::cta.global.tile.mbarrier::complete_tx::bytes "
        "[%0], [%1, {%2, %3}], [%4];"
        :: "r"(smem), "l"(tm), "r"(x), "r"(y), "r"(mbar) : "memory");
}

// ---------------------------------------------------------------------------
// Merged fp32->fp16 convert (unchanged from R16)
// ---------------------------------------------------------------------------
#define N1 (MROWS * DD)
#define N2 (QKVN * DD)
#define N3 (DD * DD)
#define NTOT (N1 + N2 + N3)

__global__ __launch_bounds__(256) void cvt_all_kernel(
    const float* __restrict__ x, const float* __restrict__ wqkv,
    const float* __restrict__ wo,
    __half* __restrict__ dx, __half* __restrict__ dwqkv, __half* __restrict__ dwo)
{
    int i = (blockIdx.x * 256 + threadIdx.x) * 8;
    if (i >= NTOT) return;
    const float* src;
    __half* dst;
    if (i < N1)           { src = x + i;              dst = dx + i; }
    else if (i < N1 + N2) { src = wqkv + (i - N1);    dst = dwqkv + (i - N1); }
    else                  { src = wo + (i - N1 - N2); dst = dwo + (i - N1 - N2); }
    float4 v0 = *reinterpret_cast<const float4*>(src);
    float4 v1 = *reinterpret_cast<const float4*>(src + 4);
    uint4 u;
    u.x = pack_h2(v0.x, v0.y);
    u.y = pack_h2(v0.z, v0.w);
    u.z = pack_h2(v1.x, v1.y);
    u.w = pack_h2(v1.z, v1.w);
    *reinterpret_cast<uint4*>(dst) = u;
}

// ---------------------------------------------------------------------------
// fp16 GEMM (m16n8k16), 128x256 CTA tile, BK=64, 3-stage cp.async pipeline —
// UNCHANGED from R16 winner.
// ---------------------------------------------------------------------------
#define GH 72
#define GSTG_H ((128 + 256) * GH)
#define D_ST 3
#define GSMB (D_ST * GSTG_H * 2)       // 165888 B

__global__ __launch_bounds__(512, 1) void gemm_f16_kernel(
    const __half* __restrict__ A, const __half* __restrict__ W,
    void* __restrict__ Cv, int M, int N, int K, int half_out)
{
    extern __shared__ __half gsm[];
    const uint32_t sb = smem_u32(gsm);

    const int tid  = threadIdx.x;
    const int warp = tid >> 5;
    const int lane = tid & 31;
    const int g    = lane >> 2;
    const int tc   = lane & 3;
    const int wm   = (warp >> 2) * 32;
    const int wn   = (warp & 3) * 64;
    const int m0   = blockIdx.y * 128;
    const int n0   = blockIdx.x * 256;

    const int lr0 = tid >> 3;
    const int sg  = (tid & 7) * 8;

    const uint32_t lqA = (uint32_t)(((lane & 15) * GH + (lane >> 4) * 8) * 2);
    const uint32_t lkB = (uint32_t)((((lane & 7) + (lane >> 4) * 8) * GH
                                    + ((lane >> 3) & 1) * 8) * 2);

    float acc[2][8][4];
#pragma unroll
    for (int mf = 0; mf < 2; mf++)
#pragma unroll
        for (int nf = 0; nf < 8; nf++)
#pragma unroll
            for (int i = 0; i < 4; i++) acc[mf][nf][i] = 0.0f;

    const int NK = K >> 6;

    auto issue = [&](int i) {
        const int k0 = i << 6;
        const uint32_t st = sb + (uint32_t)((i % D_ST) * GSTG_H * 2);
#pragma unroll
        for (int s = 0; s < 2; s++) {
            const int row = s * 64 + lr0;
            cp16s(st + (uint32_t)((row * GH + sg) * 2),
                  A + (size_t)(m0 + row) * K + k0 + sg);
        }
#pragma unroll
        for (int s = 0; s < 4; s++) {
            const int row = s * 64 + lr0;
            cp16s(st + (uint32_t)(((128 + row) * GH + sg) * 2),
                  W + (size_t)(n0 + row) * K + k0 + sg);
        }
        asm volatile("cp.async.commit_group;");
    };

    issue(0);
    if (NK > 1) issue(1);

    for (int i = 0; i < NK; i++) {
        if (i < NK - 1) { asm volatile("cp.async.wait_group 1;"); }
        else            { asm volatile("cp.async.wait_group 0;"); }
        __syncthreads();

        if (i + 2 < NK) issue(i + 2);

        const uint32_t asb = sb + (uint32_t)((i % D_ST) * GSTG_H * 2);
        const uint32_t wsb = asb + (uint32_t)(128 * GH * 2);
#pragma unroll
        for (int kk = 0; kk < 4; kk++) {
            const uint32_t kbb = (uint32_t)(kk * 32);
            uint32_t a[2][4];
            ldsm4(a[0][0], a[0][1], a[0][2], a[0][3],
                  asb + (uint32_t)(wm * GH * 2) + lqA + kbb);
            ldsm4(a[1][0], a[1][1], a[1][2], a[1][3],
                  asb + (uint32_t)((wm + 16) * GH * 2) + lqA + kbb);
#pragma unroll
            for (int nb = 0; nb < 4; nb++) {
                uint32_t b00, b01, b10, b11;
                ldsm4(b00, b01, b10, b11,
                      wsb + (uint32_t)((wn + nb * 16) * GH * 2) + lkB + kbb);
                mma_f16(acc[0][2 * nb],     a[0][0], a[0][1], a[0][2], a[0][3], b00, b01);
                mma_f16(acc[1][2 * nb],     a[1][0], a[1][1], a[1][2], a[1][3], b00, b01);
                mma_f16(acc[0][2 * nb + 1], a[0][0], a[0][1], a[0][2], a[0][3], b10, b11);
                mma_f16(acc[1][2 * nb + 1], a[1][0], a[1][1], a[1][2], a[1][3], b10, b11);
            }
        }
    }

#pragma unroll
    for (int mf = 0; mf < 2; mf++) {
        const int r0 = m0 + wm + mf * 16 + g;
#pragma unroll
        for (int nf = 0; nf < 8; nf++) {
            const int cc = n0 + wn + nf * 8 + 2 * tc;
            if (half_out) {
                __half* Ch = (__half*)Cv;
                *reinterpret_cast<uint32_t*>(&Ch[(size_t)r0 * N + cc]) =
                    pack_h2(acc[mf][nf][0], acc[mf][nf][1]);
                *reinterpret_cast<uint32_t*>(&Ch[(size_t)(r0 + 8) * N + cc]) =
                    pack_h2(acc[mf][nf][2], acc[mf][nf][3]);
            } else {
                float* Cf = (float*)Cv;
                *reinterpret_cast<float2*>(&Cf[(size_t)r0 * N + cc]) =
                    make_float2(acc[mf][nf][0], acc[mf][nf][1]);
                *reinterpret_cast<float2*>(&Cf[(size_t)(r0 + 8) * N + cc]) =
                    make_float2(acc[mf][nf][2], acc[mf][nf][3]);
            }
        }
    }
}

// ---------------------------------------------------------------------------
// Flash attention, fp16 m16n8k16, BR=256, TMA-staged Q/K/V.
// Dense SW128 smem tiles (128B rows), mbarrier 4-stage K/V ring, two tiles
// per batch. Per-warp MMA math identical to R16.
// ---------------------------------------------------------------------------
#define BR 256
#define BC 64
#define NT (LL / BC)
#define QTB 32768                  // Q tile bytes (256 x 128B)
#define KVB 8192                   // K or V stage bytes (64 x 128B)
#define SMB_Q 0
#define SMB_K QTB                  // 4 K stages
#define SMB_V (QTB + 4 * KVB)      // 4 V stages
#define SMB_BAR (QTB + 8 * KVB)    // qbar + 4 stage barriers
#define ASM_BYTES (SMB_BAR + 64)   // 98368 B

__global__ __launch_bounds__(512, 1) void attn_f16_kernel(
    const __grid_constant__ CUtensorMap tmq,
    const __grid_constant__ CUtensorMap tmkv,
    __half* __restrict__ ctx)
{
    extern __shared__ uint32_t sm[];
    const uint32_t sb = smem_u32(sm);

    const int tid  = threadIdx.x;
    const int warp = tid >> 5;
    const int lane = tid & 31;
    const int g    = lane >> 2;
    const int tc   = lane & 3;
    const int wm   = warp * 16;

    const int bh = blockIdx.y;
    const int b  = bh >> 3;
    const int h  = bh & 7;
    const int q0 = blockIdx.x * BR;

    const uint32_t qsm  = sb + SMB_Q;
    const uint32_t barQ = sb + SMB_BAR;
    const uint32_t barS = sb + SMB_BAR + 8;   // 4 x 8B

    // lane-constant fragment byte bases (dense 128B rows, pre-swizzle)
    const uint32_t qoffL = (uint32_t)((wm + (lane & 15)) * 128 + (lane >> 4) * 16);
    const uint32_t koffL = (uint32_t)(((lane & 7) + (lane >> 4) * 8) * 128
                                      + ((lane >> 3) & 1) * 16);
    const uint32_t voffL = (uint32_t)(((lane & 7) + ((lane >> 3) & 1) * 8) * 128
                                      + (lane >> 4) * 16);

    const int xq = h * DKK;            // Q x-coord (halves)
    const int xk = DD + h * DKK;       // K x-coord
    const int xv = 2 * DD + h * DKK;   // V x-coord
    const int yb = b * LL;             // row base

    // ---- init barriers, issue Q + tiles 0,1 ----
    if (tid == 0) {
        mbar_init(barQ, 1);
#pragma unroll
        for (int s = 0; s < 4; s++) mbar_init(barS + s * 8, 1);
    }
    __syncthreads();
    if (tid == 0) {
        mbar_expect(barQ, QTB);
        tma2d(qsm, &tmq, xq, yb + q0, barQ);
#pragma unroll
        for (int u = 0; u < 2; u++) {
            mbar_expect(barS + u * 8, 2 * KVB);
            tma2d(sb + SMB_K + u * KVB, &tmkv, xk, yb + u * BC, barS + u * 8);
            tma2d(sb + SMB_V + u * KVB, &tmkv, xv, yb + u * BC, barS + u * 8);
        }
    }

    float oa[8][4];
#pragma unroll
    for (int n = 0; n < 8; n++)
#pragma unroll
        for (int i = 0; i < 4; i++) oa[n][i] = 0.0f;
    float m0 = -1e30f, m1 = -1e30f;
    float l0 = 0.0f,  l1 = 0.0f;

    mbar_wait(barQ, 0);

    for (int t = 0; t < NT; t += 2) {
        // prefetch tiles t+2, t+3 (their stages were consumed last batch)
        if (tid == 0 && t + 2 < NT) {
#pragma unroll
            for (int u = 0; u < 2; u++) {
                const int tt = t + 2 + u;
                const int s  = tt & 3;
                mbar_expect(barS + s * 8, 2 * KVB);
                tma2d(sb + SMB_K + s * KVB, &tmkv, xk, yb + tt * BC, barS + s * 8);
                tma2d(sb + SMB_V + s * KVB, &tmkv, xv, yb + tt * BC, barS + s * 8);
            }
        }

#pragma unroll
        for (int u = 0; u < 2; u++) {
            const int tt = t + u;
            mbar_wait(barS + (tt & 3) * 8, (uint32_t)((tt >> 2) & 1));
            const uint32_t ks = sb + SMB_K + (uint32_t)((tt & 3) * KVB);
            const uint32_t vs = sb + SMB_V + (uint32_t)((tt & 3) * KVB);

            // S = Q @ K^T : 16x64 per warp
            float sa[8][4];
#pragma unroll
            for (int n = 0; n < 8; n++)
#pragma unroll
                for (int i = 0; i < 4; i++) sa[n][i] = 0.0f;

#pragma unroll
            for (int kk = 0; kk < 4; kk++) {
                uint32_t a0, a1, a2, a3;
                const uint32_t qo = qoffL + (uint32_t)(kk * 32);
                ldsm4(a0, a1, a2, a3, qsm + SWZ(qo));
#pragma unroll
                for (int nb = 0; nb < 4; nb++) {
                    uint32_t b00, b01, b10, b11;
                    const uint32_t ko = koffL + (uint32_t)(nb * 2048 + kk * 32);
                    ldsm4(b00, b01, b10, b11, ks + SWZ(ko));
                    mma_f16(sa[2 * nb], a0, a1, a2, a3, b00, b01);
                    mma_f16(sa[2 * nb + 1], a0, a1, a2, a3, b10, b11);
                }
            }

            // Online softmax (base-2, scale inside exp argument)
            float mx0 = -1e30f, mx1 = -1e30f;
#pragma unroll
            for (int n = 0; n < 8; n++) {
                mx0 = fmaxf(mx0, fmaxf(sa[n][0], sa[n][1]));
                mx1 = fmaxf(mx1, fmaxf(sa[n][2], sa[n][3]));
            }
            mx0 = fmaxf(mx0, __shfl_xor_sync(0xffffffffu, mx0, 1));
            mx0 = fmaxf(mx0, __shfl_xor_sync(0xffffffffu, mx0, 2));
            mx1 = fmaxf(mx1, __shfl_xor_sync(0xffffffffu, mx1, 1));
            mx1 = fmaxf(mx1, __shfl_xor_sync(0xffffffffu, mx1, 2));

            const bool upd = !__all_sync(0xffffffffu, (mx0 <= m0) & (mx1 <= m1));
            if (upd) {
                float mn0 = fmaxf(m0, mx0);
                float mn1 = fmaxf(m1, mx1);
                float alpha0 = ex2(CC * (m0 - mn0));
                float alpha1 = ex2(CC * (m1 - mn1));
                m0 = mn0; m1 = mn1;
                l0 *= alpha0;
                l1 *= alpha1;
#pragma unroll
                for (int n = 0; n < 8; n++) {
                    oa[n][0] *= alpha0; oa[n][1] *= alpha0;
                    oa[n][2] *= alpha1; oa[n][3] *= alpha1;
                }
            }

            const float nc0 = -CC * m0;
            const float nc1 = -CC * m1;
            float sum0 = 0.0f, sum1 = 0.0f;
#pragma unroll
            for (int n = 0; n < 8; n++) {
                float p0 = ex2(fmaf(CC, sa[n][0], nc0));
                float p1 = ex2(fmaf(CC, sa[n][1], nc0));
                float p2 = ex2(fmaf(CC, sa[n][2], nc1));
                float p3 = ex2(fmaf(CC, sa[n][3], nc1));
                sum0 += p0 + p1;
                sum1 += p2 + p3;
                sa[n][0] = p0; sa[n][1] = p1; sa[n][2] = p2; sa[n][3] = p3;
            }
            l0 += sum0;
            l1 += sum1;

            // O += P @ V
#pragma unroll
            for (int kk = 0; kk < 4; kk++) {
                uint32_t a0 = pack_h2(sa[2 * kk][0],     sa[2 * kk][1]);
                uint32_t a1 = pack_h2(sa[2 * kk][2],     sa[2 * kk][3]);
                uint32_t a2 = pack_h2(sa[2 * kk + 1][0], sa[2 * kk + 1][1]);
                uint32_t a3 = pack_h2(sa[2 * kk + 1][2], sa[2 * kk + 1][3]);
#pragma unroll
                for (int nb = 0; nb < 4; nb++) {
                    uint32_t b00, b01, b10, b11;
                    const uint32_t vo = voffL + (uint32_t)(kk * 2048 + nb * 32);
                    ldsm4t(b00, b01, b10, b11, vs + SWZ(vo));
                    mma_f16(oa[2 * nb], a0, a1, a2, a3, b00, b01);
                    mma_f16(oa[2 * nb + 1], a0, a1, a2, a3, b10, b11);
                }
            }
        }

        __syncthreads();   // all threads done with stages t&3,(t+1)&3
    }

    // Finalize l, normalize, write ctx (fp16)
    l0 += __shfl_xor_sync(0xffffffffu, l0, 1);
    l0 += __shfl_xor_sync(0xffffffffu, l0, 2);
    l1 += __shfl_xor_sync(0xffffffffu, l1, 1);
    l1 += __shfl_xor_sync(0xffffffffu, l1, 2);
    float inv0 = 1.0f / l0;
    float inv1 = 1.0f / l1;

    const int r0 = q0 + wm + g;
    const int r1 = r0 + 8;
#pragma unroll
    for (int n = 0; n < 8; n++) {
        *reinterpret_cast<uint32_t*>(
            &ctx[(size_t)(b * LL + r0) * DD + h * DKK + n * 8 + 2 * tc]) =
            pack_h2(oa[n][0] * inv0, oa[n][1] * inv0);
        *reinterpret_cast<uint32_t*>(
            &ctx[(size_t)(b * LL + r1) * DD + h * DKK + n * 8 + 2 * tc]) =
            pack_h2(oa[n][2] * inv1, oa[n][3] * inv1);
    }
}

// ---------------------------------------------------------------------------
// Host: tensor-map encode via driver entry point (no -lcuda link dependency)
// ---------------------------------------------------------------------------
typedef CUresult (*EncFn)(CUtensorMap*, CUtensorMapDataType, cuuint32_t, void*,
                          const cuuint64_t*, const cuuint64_t*, const cuuint32_t*,
                          const cuuint32_t*, CUtensorMapInterleave, CUtensorMapSwizzle,
                          CUtensorMapL2promotion, CUtensorMapFloatOOBfill);

static EncFn get_encode_fn() {
    static EncFn fn = nullptr;
    if (!fn) {
        void* p = nullptr;
        cudaDriverEntryPointQueryResult qres;
        cudaGetDriverEntryPoint("cuTensorMapEncodeTiled", &p,
                                cudaEnableDefault, &qres);
        fn = (EncFn)p;
    }
    return fn;
}

static void make_map(CUtensorMap* tm, void* gaddr, uint32_t box0, uint32_t box1) {
    cuuint64_t dims[2]    = {(cuuint64_t)QKVN, (cuuint64_t)MROWS};
    cuuint64_t strides[1] = {(cuuint64_t)QKVN * 2};
    cuuint32_t box[2]     = {box0, box1};
    cuuint32_t es[2]      = {1, 1};
    get_encode_fn()(tm, CU_TENSOR_MAP_DATA_TYPE_FLOAT16, 2, gaddr,
                    dims, strides, box, es,
                    CU_TENSOR_MAP_INTERLEAVE_NONE, CU_TENSOR_MAP_SWIZZLE_128B,
                    CU_TENSOR_MAP_L2_PROMOTION_L2_128B,
                    CU_TENSOR_MAP_FLOAT_OOB_FILL_NONE);
}

// ---------------------------------------------------------------------------
extern "C" void kernel_launch(void* const* d_in, const int* in_sizes, int n_in,
                              void* d_out, int out_size)
{
    const float* x     = (const float*)d_in[0];
    const float* w_qkv = (const float*)d_in[1];
    const float* w_o   = (const float*)d_in[2];
    float* out = (float*)d_out;

    __half *x_p, *wqkv_p, *wo_p, *qkv_p, *ctx_p;
    cudaGetSymbolAddress((void**)&x_p,    g_x);
    cudaGetSymbolAddress((void**)&wqkv_p, g_wqkv);
    cudaGetSymbolAddress((void**)&wo_p,   g_wo);
    cudaGetSymbolAddress((void**)&qkv_p,  g_qkv);
    cudaGetSymbolAddress((void**)&ctx_p,  g_ctx);
    cudaFuncSetAttribute(gemm_f16_kernel, cudaFuncAttributeMaxDynamicSharedMemorySize, GSMB);
    cudaFuncSetAttribute(attn_f16_kernel, cudaFuncAttributeMaxDynamicSharedMemorySize, ASM_BYTES);

    CUtensorMap tmq, tmkv;
    make_map(&tmq,  qkv_p, 64, 256);   // Q box: 64 halves x 256 rows
    make_map(&tmkv, qkv_p, 64, 64);    // K/V box: 64 halves x 64 rows

    // 0) fp32 -> fp16 conversion
    cvt_all_kernel<<<(NTOT / 8 + 255) / 256, 256>>>(x, w_qkv, w_o, x_p, wqkv_p, wo_p);

    // 1) qkv = x @ w_qkv^T : [8192, 1536], fp16 out
    {
        dim3 grid(QKVN / 256, MROWS / 128);
        gemm_f16_kernel<<<grid, 512, GSMB>>>(x_p, wqkv_p, qkv_p, MROWS, QKVN, DD, 1);
    }
    // 2) attention -> ctx (fp16), TMA staging
    {
        dim3 grid(LL / BR, BB * HH);
        attn_f16_kernel<<<grid, 512, ASM_BYTES>>>(tmq, tmkv, ctx_p);
    }
    // 3) out = ctx @ w_o^T : [8192, 512], fp32 out
    {
        dim3 grid(DD / 256, MROWS / 128);
        gemm_f16_kernel<<<grid, 512, GSMB>>>(ctx_p, wo_p, out, MROWS, DD, DD, 0);
    }
}